// round 16
// baseline (speedup 1.0000x reference)
#include <cuda_runtime.h>
#include <cuda_fp16.h>
#include <math.h>
#include <stdint.h>

// ---------------- problem constants ----------------
#define N_IMG 4
#define CIN   512
#define HH    64
#define WW    64
#define NPOS  (HH*WW)            // 4096
#define NANCH 9
#define A_TOT (NPOS*NANCH)       // 36864
#define PRE_NMS  3000
#define POST_NMS 300
#define NMS_WORDS 94             // ceil(3000/32)
#define NMS_THRESH 0.7f
#define MIN_SIZE 16.0f

// ---------------- d_out layout (floats), reference return order ----------------
#define SZ_LOCS   (N_IMG*A_TOT*4)            // 589824
#define OFF_LOCS  0
#define SZ_SCORES (N_IMG*A_TOT*2)            // 294912
#define OFF_SCORES (OFF_LOCS+SZ_LOCS)        // 589824
#define SZ_ROIS   (N_IMG*POST_NMS*4)         // 4800
#define OFF_ROIS  (OFF_SCORES+SZ_SCORES)     // 884736
#define SZ_RIDX   (N_IMG*POST_NMS)           // 1200
#define OFF_RIDX  (OFF_ROIS+SZ_ROIS)         // 889536
#define OFF_ANCHOR (OFF_RIDX+SZ_RIDX)        // 890736  (size 147456)

// ---------------- device scratch ----------------
__device__ float               g_hidden[N_IMG*CIN*NPOS];        // 33.5 MB
__device__ float4              g_rois_all[N_IMG*A_TOT];         // 2.36 MB
__device__ unsigned long long  g_keys[N_IMG*A_TOT];             // 1.2 MB
__device__ unsigned long long  g_sel[N_IMG*3072];
__device__ unsigned long long  g_thresh[N_IMG];
__device__ unsigned            g_cnt[N_IMG];
__device__ float4              g_boxes_top[N_IMG*PRE_NMS];      // 192 KB
__device__ float               g_scores_top[N_IMG*PRE_NMS];     // 48 KB
__device__ unsigned            g_mask[(size_t)N_IMG*PRE_NMS*NMS_WORDS]; // 4.5 MB

// split-fp16 weights (scaled x64), pre-swizzled smem-tile layout:
// [ot128(4)][ch(72)] tiles of 16KB (128 oc rows x 128B, SW128 swizzled).
// SW128 swizzle is row-local, so a 64-oc half-tile = base + half*8192.
#define NCHUNK 72
__device__ uint4 g_wt_hi[4*NCHUNK*1024];   // 4.7 MB
__device__ uint4 g_wt_lo[4*NCHUNK*1024];   // 4.7 MB

// split-fp16 transposed features: [img][pos][cin] fp16
__device__ __half g_xt_hi[(size_t)N_IMG*NPOS*CIN];   // 16.8 MB
__device__ __half g_xt_lo[(size_t)N_IMG*NPOS*CIN];   // 16.8 MB

#define NOUT 54

#define W_SCALE 64.0f
#define W_INV   (1.0f/64.0f)

#define SWZ128(o) ((o) ^ (((o) >> 3) & 0x70))

__device__ __forceinline__ unsigned smem_u32(const void* p) {
    unsigned a;
    asm("{ .reg .u64 t; cvta.to.shared.u64 t, %1; cvt.u32.u64 %0, t; }"
        : "=r"(a) : "l"(p));
    return a;
}

__device__ __forceinline__ void cp_async16(unsigned dst, const void* src, unsigned src_sz)
{
    asm volatile("cp.async.cg.shared.global [%0], [%1], 16, %2;"
                 :: "r"(dst), "l"(src), "r"(src_sz) : "memory");
}
#define CP_COMMIT() asm volatile("cp.async.commit_group;" ::: "memory")
#define CP_WAIT(n)  asm volatile("cp.async.wait_group %0;" :: "n"(n) : "memory")

__device__ __forceinline__ void ldsm4(unsigned& r0, unsigned& r1,
                                      unsigned& r2, unsigned& r3, unsigned addr)
{
    asm volatile("ldmatrix.sync.aligned.m8n8.x4.shared.b16 {%0,%1,%2,%3}, [%4];"
                 : "=r"(r0), "=r"(r1), "=r"(r2), "=r"(r3) : "r"(addr));
}

// fp32-accumulator mma (main term)
__device__ __forceinline__ void mma16816(float* c, const unsigned* a, const unsigned* b)
{
    asm volatile(
        "mma.sync.aligned.m16n8k16.row.col.f32.f16.f16.f32 "
        "{%0,%1,%2,%3}, {%4,%5,%6,%7}, {%8,%9}, {%0,%1,%2,%3};"
        : "+f"(c[0]), "+f"(c[1]), "+f"(c[2]), "+f"(c[3])
        : "r"(a[0]), "r"(a[1]), "r"(a[2]), "r"(a[3]), "r"(b[0]), "r"(b[1]));
}

// fp16-accumulator mma (cross terms)
__device__ __forceinline__ void mma16816h(unsigned* c, const unsigned* a, const unsigned* b)
{
    asm volatile(
        "mma.sync.aligned.m16n8k16.row.col.f16.f16.f16.f16 "
        "{%0,%1}, {%2,%3,%4,%5}, {%6,%7}, {%0,%1};"
        : "+r"(c[0]), "+r"(c[1])
        : "r"(a[0]), "r"(a[1]), "r"(a[2]), "r"(a[3]), "r"(b[0]), "r"(b[1]));
}

// =================================================================
// weight prep (x64 scale, split fp16, pre-swizzled) — unchanged
// =================================================================
__global__ void wprep_kernel(const float* __restrict__ W1)
{
    int t = blockIdx.x * blockDim.x + threadIdx.x;
    if (t >= 4*NCHUNK*128*32) return;
    int c2 = t & 31;
    int r  = (t >> 5) & 127;
    int tc = t >> 12;
    int ch = tc % NCHUNK;
    int ot = tc / NCHUNK;
    int kk  = ch >> 3;
    int ccb = ch & 7;
    int c  = c2 * 2;
    int cc = ccb*64 + c;
    int oc = ot*128 + r;

    float w0 = W1[(size_t)oc*4608 + (size_t)cc*9 + kk] * W_SCALE;
    float w1 = W1[(size_t)oc*4608 + (size_t)(cc+1)*9 + kk] * W_SCALE;
    __half h0 = __float2half_rn(w0), h1 = __float2half_rn(w1);
    __half l0 = __float2half_rn(w0 - __half2float(h0));
    __half l1 = __float2half_rn(w1 - __half2float(h1));

    unsigned off = (unsigned)(r*128 + c*2);
    off = SWZ128(off);
    size_t base = (size_t)tc * 16384;
    *reinterpret_cast<__half2*>(reinterpret_cast<char*>(g_wt_hi) + base + off) =
        __halves2half2(h0, h1);
    *reinterpret_cast<__half2*>(reinterpret_cast<char*>(g_wt_lo) + base + off) =
        __halves2half2(l0, l1);
}

// =================================================================
// x split + transpose
// =================================================================
__global__ void xsplit_kernel(const float* __restrict__ x)
{
    __shared__ float tile[32][33];
    const int p0  = blockIdx.x * 32;
    const int c0  = blockIdx.y * 32;
    const int img = blockIdx.z;
    const int tx = threadIdx.x, ty = threadIdx.y;

#pragma unroll
    for (int i = 0; i < 4; i++) {
        int c = c0 + ty + i*8;
        tile[ty + i*8][tx] = x[((size_t)img*CIN + c)*NPOS + p0 + tx];
    }
    __syncthreads();

#pragma unroll
    for (int i = 0; i < 4; i++) {
        int p = p0 + ty + i*8;
        float v = tile[tx][ty + i*8];
        __half h = __float2half_rn(v);
        __half l = __float2half_rn(v - __half2float(h));
        size_t o = ((size_t)img*NPOS + p)*CIN + c0 + tx;
        g_xt_hi[o] = h;
        g_xt_lo[o] = l;
    }
}

// =================================================================
// HMMA split-fp16 conv: 64 oc x 64 pos tiles, 3-stage ring, 32 KB
// stages -> 96 KB smem, 2 CTAs/SM, ONE barrier per chunk.
// Per-output mma chain order identical -> bit-identical results.
// =================================================================
#define BUF_STRIDE 32768
#define NSTAGE 3
#define SM_AHI 0
#define SM_ALO 8192
#define SM_BHI 16384
#define SM_BLO 24576
#define SM_CONV_TOTAL (NSTAGE*BUF_STRIDE)     // 98304

__global__ void __launch_bounds__(256, 2) conv_hmma_kernel(const float* __restrict__ b1)
{
    extern __shared__ char smem[];
    const unsigned sbase = smem_u32(smem);
    const int tid  = threadIdx.x;
    const int wid  = tid >> 5;
    const int lane = tid & 31;
    const int ot   = blockIdx.x;          // 64-oc tile 0..7
    const int pt   = blockIdx.y;          // pos tile 0..63 (1 image row)
    const int img  = blockIdx.z;

    const int wm = wid >> 2;              // 0..1 : oc block of 32
    const int wn = wid & 3;               // 0..3 : pos block of 16

    const int sel = lane >> 3;
    const int l7  = lane & 7;

    const int pos0 = pt * 64;
    // B-issue mapping: tid -> (pos 0..63, khalf 0..1, arr 0..1)
    const int bp  = tid & 63;
    const int kh  = (tid >> 6) & 1;
    const int arr = tid >> 7;             // 0: hi, 1: lo

    float acc[2][2][4];
    unsigned accH[2][2][2];
#pragma unroll
    for (int mt = 0; mt < 2; mt++)
#pragma unroll
        for (int nt = 0; nt < 2; nt++) {
#pragma unroll
            for (int k = 0; k < 4; k++) acc[mt][nt][k] = 0.f;
            accH[mt][nt][0] = 0u;
            accH[mt][nt][1] = 0u;
        }

    const unsigned a_row  = (unsigned)(wm*32 + (sel & 1)*8 + l7);
    const unsigned a_colb = (unsigned)((sel >> 1) * 16);
    const unsigned b_row  = (unsigned)(wn*16 + (sel >> 1)*8 + l7);
    const unsigned b_colb = (unsigned)((sel & 1) * 16);

    const __half* xh_img = g_xt_hi + (size_t)img*NPOS*CIN;
    const __half* xl_img = g_xt_lo + (size_t)img*NPOS*CIN;

    // weight half-tile base (64 rows x 128B within the 128-row tile)
    const size_t wbase_ch0 = ((size_t)(ot >> 1)*NCHUNK) * 1024;
    const size_t whalf     = (size_t)(ot & 1) * 512;      // in uint4 units

    auto issue_chunk = [&](int ch) {
        const unsigned bb = sbase + (unsigned)(ch % NSTAGE)*BUF_STRIDE;
        // A: 512 uint4 each hi/lo; 256 thr x 2
        {
            const uint4* sh = g_wt_hi + wbase_ch0 + (size_t)ch*1024 + whalf;
            const uint4* sl = g_wt_lo + wbase_ch0 + (size_t)ch*1024 + whalf;
#pragma unroll
            for (int i = 0; i < 2; i++) {
                cp_async16(bb + SM_AHI + (tid + i*256)*16, sh + tid + i*256, 16u);
                cp_async16(bb + SM_ALO + (tid + i*256)*16, sl + tid + i*256, 16u);
            }
        }
        // B: per (pos, khalf, arr): 4 x 16B
        {
            const int kk  = ch >> 3;
            const int ccb = ch & 7;
            const int dy  = kk / 3 - 1;
            const int dx  = kk % 3 - 1;
            const int gy  = pt + dy;
            const int gx  = bp + dx;
            const bool valid = (gy >= 0) && (gy < HH) && (gx >= 0) && (gx < WW);
            const unsigned sz = valid ? 16u : 0u;
            const size_t srcoff = ((size_t)(gy*WW + gx))*CIN + ccb*64 + kh*32;
            const __half* src = (arr == 0 ? xh_img : xl_img) + srcoff;
            const unsigned dbase = (arr == 0 ? SM_BHI : SM_BLO);
#pragma unroll
            for (int k = 0; k < 4; k++) {
                unsigned d = SWZ128((unsigned)(bp*128 + kh*64 + k*16));
                cp_async16(bb + dbase + d, src + k*8, sz);
            }
        }
        CP_COMMIT();
    };

    issue_chunk(0);
    issue_chunk(1);

    for (int ch = 0; ch < NCHUNK; ch++) {
        CP_WAIT(1);                 // group ch complete (2 in flight max)
        __syncthreads();            // single barrier per chunk (3-stage ring)
        if (ch + 2 < NCHUNK) issue_chunk(ch + 2);
        else CP_COMMIT();           // keep wait_group accounting uniform

        const unsigned bb = sbase + (unsigned)(ch % NSTAGE)*BUF_STRIDE;
#pragma unroll
        for (int ks = 0; ks < 4; ks++) {
            const unsigned kcol = (unsigned)(ks * 32);
            unsigned bh[4], bl[4];
            {
                unsigned off0 = SWZ128(b_row*128 + kcol + b_colb);
                ldsm4(bh[0], bh[1], bh[2], bh[3], bb + SM_BHI + off0);
                ldsm4(bl[0], bl[1], bl[2], bl[3], bb + SM_BLO + off0);
            }
#pragma unroll
            for (int mt = 0; mt < 2; mt++) {
                unsigned aoff = SWZ128((a_row + mt*16)*128 + kcol + a_colb);
                unsigned ah[4], al[4];
                ldsm4(ah[0], ah[1], ah[2], ah[3], bb + SM_AHI + aoff);
                ldsm4(al[0], al[1], al[2], al[3], bb + SM_ALO + aoff);
#pragma unroll
                for (int nt = 0; nt < 2; nt++) {
                    mma16816(acc[mt][nt], ah, &bh[nt*2]);     // wh*xh  (fp32 acc)
                    mma16816h(accH[mt][nt], ah, &bl[nt*2]);   // wh*xl  (fp16 acc)
                    mma16816h(accH[mt][nt], al, &bh[nt*2]);   // wl*xh  (fp16 acc)
                }
            }
        }
    }

    const int mrow = lane >> 2;
    const int ncol = (lane & 3) * 2;
#pragma unroll
    for (int mt = 0; mt < 2; mt++) {
        const int ocA = ot*64 + wm*32 + mt*16 + mrow;
        const int ocB = ocA + 8;
        const float biasA = b1[ocA];
        const float biasB = b1[ocB];
#pragma unroll
        for (int nt = 0; nt < 2; nt++) {
            const int pos = pos0 + wn*16 + nt*8 + ncol;
            __half2 cr01 = *reinterpret_cast<__half2*>(&accH[mt][nt][0]);
            __half2 cr23 = *reinterpret_cast<__half2*>(&accH[mt][nt][1]);
            float v0 = (acc[mt][nt][0] + __low2float(cr01))  * W_INV + biasA;
            float v1 = (acc[mt][nt][1] + __high2float(cr01)) * W_INV + biasA;
            float v2 = (acc[mt][nt][2] + __low2float(cr23))  * W_INV + biasB;
            float v3 = (acc[mt][nt][3] + __high2float(cr23)) * W_INV + biasB;
            v0 = v0 > 0.f ? v0 : 0.f;
            v1 = v1 > 0.f ? v1 : 0.f;
            v2 = v2 > 0.f ? v2 : 0.f;
            v3 = v3 > 0.f ? v3 : 0.f;
            *reinterpret_cast<float2*>(
                g_hidden + ((size_t)img*CIN + ocA)*NPOS + pos) = make_float2(v0, v1);
            *reinterpret_cast<float2*>(
                g_hidden + ((size_t)img*CIN + ocB)*NPOS + pos) = make_float2(v2, v3);
        }
    }
}

// =================================================================
// 1x1 convs: output-split (3 groups of 18), sequential channel order
// =================================================================
__global__ __launch_bounds__(192) void conv1x1_kernel(
    const float* __restrict__ Wl, const float* __restrict__ bl,
    const float* __restrict__ Ws, const float* __restrict__ bs,
    float* __restrict__ out)
{
    __shared__ float Wc[64][NOUT];
    const int tid = threadIdx.x;
    const int lp  = tid & 63;
    const int og  = tid >> 6;             // 0..2
    const int o0  = og * 18;
    const int img = blockIdx.y;
    const int pos = blockIdx.x * 64 + lp;

    float acc[18];
#pragma unroll
    for (int o = 0; o < 18; o++) acc[o] = 0.f;

    const float* hid = g_hidden + (size_t)img * CIN * NPOS;

    for (int c0 = 0; c0 < CIN; c0 += 64) {
        for (int idx = tid; idx < 64*NOUT; idx += 192) {
            int c = idx / NOUT;
            int o = idx - c*NOUT;
            Wc[c][o] = (o < 36) ? Wl[(size_t)o*CIN + c0 + c]
                                : Ws[(size_t)(o-36)*CIN + c0 + c];
        }
        __syncthreads();
#pragma unroll 8
        for (int c = 0; c < 64; c++) {
            float h = hid[(size_t)(c0+c)*NPOS + pos];
#pragma unroll
            for (int o = 0; o < 18; o++) acc[o] += h * Wc[c][o0 + o];
        }
        __syncthreads();
    }

#pragma unroll
    for (int o = 0; o < 18; o++) {
        int oo = o0 + o;
        if (oo < 36)
            out[OFF_LOCS + (size_t)img*A_TOT*4 + (size_t)pos*36 + oo] = acc[o] + bl[oo];
        else
            out[OFF_SCORES + (size_t)img*A_TOT*2 + (size_t)pos*18 + (oo-36)] = acc[o] + bs[oo-36];
    }
}

// =================================================================
// anchor generation
// =================================================================
__global__ void anchor_kernel(float* __restrict__ out)
{
    int i = blockIdx.x * blockDim.x + threadIdx.x;
    if (i >= A_TOT) return;
    int a   = i % 9;
    int pos = i / 9;
    int y = pos / WW, x = pos % WW;
    int ri = a / 3, si = a % 3;
    double rr = (ri == 0) ? 0.5 : (ri == 1 ? 1.0 : 2.0);
    double ss = (si == 0) ? 8.0 : (si == 1 ? 16.0 : 32.0);
    double h = 16.0 * ss * sqrt(rr);
    double w = 16.0 * ss * sqrt(1.0 / rr);
    float ymin = (float)(8.0 - h*0.5);
    float xmin = (float)(8.0 - w*0.5);
    float ymax = (float)(8.0 + h*0.5);
    float xmax = (float)(8.0 + w*0.5);
    float sy = (float)y * 16.0f, sx = (float)x * 16.0f;
    reinterpret_cast<float4*>(out + OFF_ANCHOR)[i] =
        make_float4(sy + ymin, sx + xmin, sy + ymax, sx + xmax);
}

// =================================================================
// proposal: loc2bbox + clip + min-size + softmax + sort key
// =================================================================
__device__ __forceinline__ float read_dim(const void* p)
{
    int v = *(const int*)p;
    if (v > 0 && v < (1 << 20)) return (float)v;
    return *(const float*)p;
}

__global__ void proposal_kernel(const float* __restrict__ out,
                                const void* __restrict__ p_ih,
                                const void* __restrict__ p_iw)
{
    int t = blockIdx.x * blockDim.x + threadIdx.x;
    if (t >= N_IMG * A_TOT) return;
    int img = t / A_TOT;
    int i   = t - img * A_TOT;

    const float4 anc = reinterpret_cast<const float4*>(out + OFF_ANCHOR)[i];
    const float* loc = out + OFF_LOCS + (size_t)img*A_TOT*4 + (size_t)i*4;
    const float l0 = loc[0], l1 = loc[1], l2 = loc[2], l3 = loc[3];
    const float* sc = out + OFF_SCORES + (size_t)img*A_TOT*2 + (size_t)i*2;
    const float s0 = sc[0], s1 = sc[1];

    float h  = anc.z - anc.x, w = anc.w - anc.y;
    float cy = anc.x + 0.5f*h, cx = anc.y + 0.5f*w;
    float ncy = l0*h + cy, ncx = l1*w + cx;
    float nh  = expf(l2)*h,  nw  = expf(l3)*w;

    float fh = read_dim(p_ih), fw = read_dim(p_iw);
    float y1 = fminf(fmaxf(ncy - 0.5f*nh, 0.f), fh);
    float x1 = fminf(fmaxf(ncx - 0.5f*nw, 0.f), fw);
    float y2 = fminf(fmaxf(ncy + 0.5f*nh, 0.f), fh);
    float x2 = fminf(fmaxf(ncx + 0.5f*nw, 0.f), fw);

    bool ok = ((y2 - y1) >= MIN_SIZE) && ((x2 - x1) >= MIN_SIZE);

    float m  = fmaxf(s0, s1);
    float e0 = expf(s0 - m), e1 = expf(s1 - m);
    float fg = e1 / (e0 + e1);
    float score = ok ? fg : -INFINITY;

    g_rois_all[(size_t)img*A_TOT + i] = make_float4(y1, x1, y2, x2);

    unsigned u    = __float_as_uint(score);
    unsigned mkey = u ^ ((u >> 31) ? 0xFFFFFFFFu : 0x80000000u);
    unsigned dkey = ~mkey;
    g_keys[(size_t)img*A_TOT + i] = ((unsigned long long)dkey << 32) | (unsigned)i;
}

// =================================================================
// radix-select: exact 3000th-smallest key per image (per-warp hists)
// =================================================================
__global__ __launch_bounds__(1024) void select_kernel()
{
    __shared__ unsigned hist[32][256];
    __shared__ unsigned cnt[256];
    __shared__ unsigned long long s_prefix;
    __shared__ int s_remaining;

    const int img  = blockIdx.x;
    const int tid  = threadIdx.x;
    const int wrp  = tid >> 5;
    const unsigned long long* keys = g_keys + (size_t)img*A_TOT;

    unsigned long long kreg[36];
#pragma unroll
    for (int j = 0; j < 36; j++) kreg[j] = keys[tid + j*1024];

    if (tid == 0) { s_prefix = 0; s_remaining = PRE_NMS; g_cnt[img] = 0; }
    __syncthreads();

    for (int s = 0; s < 8; s++) {
        for (int b = tid; b < 32*256; b += 1024)
            reinterpret_cast<unsigned*>(hist)[b] = 0;
        __syncthreads();
        const unsigned long long pfx = s_prefix;
        const int shift = 56 - 8*s;
#pragma unroll
        for (int j = 0; j < 36; j++) {
            unsigned long long k = kreg[j];
            bool match = (s == 0) || ((k >> (64 - 8*s)) == pfx);
            if (match) atomicAdd(&hist[wrp][(unsigned)((k >> shift) & 0xFF)], 1u);
        }
        __syncthreads();
        if (tid < 256) {
            unsigned c = 0;
#pragma unroll
            for (int w = 0; w < 32; w++) c += hist[w][tid];
            cnt[tid] = c;
        }
        __syncthreads();
        if (tid == 0) {
            unsigned c = 0;
            int b = 0;
            int rem = s_remaining;
            for (; b < 256; b++) {
                c += cnt[b];
                if ((int)c >= rem) break;
            }
            s_remaining = rem - (int)(c - cnt[b]);
            s_prefix = (s_prefix << 8) | (unsigned long long)b;
        }
        __syncthreads();
    }
    if (tid == 0) g_thresh[img] = s_prefix;
}

// =================================================================
// compact keys <= threshold (exactly 3000, unordered)
// =================================================================
__global__ void compact_kernel()
{
    const int img = blockIdx.y;
    const int i   = blockIdx.x * 256 + threadIdx.x;
    const int lane = threadIdx.x & 31;

    unsigned long long T = g_thresh[img];
    unsigned long long k = g_keys[(size_t)img*A_TOT + i];
    bool sel = (k <= T);

    unsigned mask = __ballot_sync(0xFFFFFFFFu, sel);
    if (sel) {
        int leader = __ffs(mask) - 1;
        unsigned base = 0;
        if (lane == leader) base = atomicAdd(&g_cnt[img], (unsigned)__popc(mask));
        base = __shfl_sync(0xFFFFFFFFu, base, leader);
        int off = __popc(mask & ((1u << lane) - 1u));
        g_sel[(size_t)img*3072 + base + off] = k;
    }
}

// =================================================================
// single-block bitonic sort of 3000 keys (pad to 4096), ascending
// =================================================================
__global__ __launch_bounds__(1024) void sortblk_kernel()
{
    __shared__ unsigned long long sk[4096];
    const int img = blockIdx.x;
    const int tid = threadIdx.x;

#pragma unroll
    for (int j = 0; j < 4; j++) {
        int i = tid + j*1024;
        sk[i] = (i < PRE_NMS) ? g_sel[(size_t)img*3072 + i] : ~0ULL;
    }
    __syncthreads();

    for (int k = 2; k <= 4096; k <<= 1) {
        for (int j = k >> 1; j > 0; j >>= 1) {
#pragma unroll
            for (int t = 0; t < 2; t++) {
                int tt  = tid + t*1024;
                int i   = ((tt & ~(j - 1)) << 1) | (tt & (j - 1));
                int ixj = i | j;
                bool up = ((i & k) == 0);
                unsigned long long a = sk[i], b = sk[ixj];
                if ((a > b) == up) { sk[i] = b; sk[ixj] = a; }
            }
            __syncthreads();
        }
    }

#pragma unroll
    for (int j = 0; j < 3; j++) {
        int i = tid + j*1024;
        if (i < PRE_NMS) g_keys[(size_t)img*A_TOT + i] = sk[i];
    }
}

// =================================================================
// gather top-3000 boxes + scores
// =================================================================
__global__ void gather_kernel()
{
    int t = blockIdx.x * blockDim.x + threadIdx.x;
    if (t >= N_IMG * PRE_NMS) return;
    int img = t / PRE_NMS;
    int i   = t - img * PRE_NMS;
    unsigned long long key = g_keys[(size_t)img*A_TOT + i];
    unsigned idx = (unsigned)(key & 0xFFFFFFFFu);
    g_boxes_top[t] = g_rois_all[(size_t)img*A_TOT + idx];
    unsigned dkey = (unsigned)(key >> 32);
    unsigned mkey = ~dkey;
    unsigned u = (mkey & 0x80000000u) ? (mkey ^ 0x80000000u) : ~mkey;
    g_scores_top[t] = __uint_as_float(u);
}

// =================================================================
// NMS suppression bitmask; sub-diagonal blocks just write zeros
// =================================================================
__global__ __launch_bounds__(64) void mask_kernel()
{
    const int img  = blockIdx.z;
    const int rowb = blockIdx.y * 64;
    const int colb = blockIdx.x * 64;
    const int t = threadIdx.x;

    if (colb + 63 <= rowb) {
        int row = rowb + t;
        if (row < PRE_NMS) {
            unsigned* mrow = g_mask + ((size_t)img*PRE_NMS + row) * NMS_WORDS;
            int wi = colb >> 5;
            mrow[wi] = 0u;
            if (wi + 1 < NMS_WORDS) mrow[wi + 1] = 0u;
        }
        return;
    }

    __shared__ float4 cb[64];
    int col0 = colb + t;
    cb[t] = (col0 < PRE_NMS) ? g_boxes_top[(size_t)img*PRE_NMS + col0]
                             : make_float4(0.f, 0.f, 0.f, 0.f);
    __syncthreads();

    int row = rowb + t;
    if (row >= PRE_NMS) return;
    float4 rb = g_boxes_top[(size_t)img*PRE_NMS + row];
    float ra = fmaxf(rb.z - rb.x, 0.f) * fmaxf(rb.w - rb.y, 0.f);

    unsigned w0 = 0, w1 = 0;
#pragma unroll 4
    for (int c = 0; c < 64; c++) {
        int col = colb + c;
        if (col >= PRE_NMS || col <= row) continue;
        float4 b = cb[c];
        float yy1 = fmaxf(rb.x, b.x), xx1 = fmaxf(rb.y, b.y);
        float yy2 = fminf(rb.z, b.z), xx2 = fminf(rb.w, b.w);
        float inter = fmaxf(yy2 - yy1, 0.f) * fmaxf(xx2 - xx1, 0.f);
        float ba = fmaxf(b.z - b.x, 0.f) * fmaxf(b.w - b.y, 0.f);
        float iou = inter / (ra + ba - inter + 1e-9f);
        if (iou > NMS_THRESH) {
            if (c < 32) w0 |= 1u << c; else w1 |= 1u << (c - 32);
        }
    }
    unsigned* mrow = g_mask + ((size_t)img*PRE_NMS + row) * NMS_WORDS;
    int wi = colb >> 5;
    mrow[wi] = w0;
    if (wi + 1 < NMS_WORDS) mrow[wi + 1] = w1;
}

// =================================================================
// zero rois region + write roi_indices
// =================================================================
__global__ void fill_kernel(float* __restrict__ out)
{
    int t = blockIdx.x * blockDim.x + threadIdx.x;
    if (t < SZ_ROIS) out[OFF_ROIS + t] = 0.f;
    else if (t < SZ_ROIS + SZ_RIDX) {
        int i = t - SZ_ROIS;
        out[OFF_RIDX + i] = (float)(i / POST_NMS);
    }
}

// =================================================================
// sequential greedy NMS scan, 8-deep software-pipelined mask loads
// =================================================================
#define SCAN_D 8
__global__ void scan_kernel(float* __restrict__ out)
{
    const int img  = blockIdx.x;
    const int lane = threadIdx.x;

    unsigned sup0, sup1, sup2;
    {
        unsigned v[3];
#pragma unroll
        for (int s = 0; s < 3; s++) {
            unsigned vv = 0;
            int w = s*32 + lane;
            for (int b = 0; b < 32; b++) {
                int i = w*32 + b;
                if (i < PRE_NMS && g_scores_top[(size_t)img*PRE_NMS + i] == -INFINITY)
                    vv |= 1u << b;
            }
            v[s] = vv;
        }
        sup0 = v[0]; sup1 = v[1]; sup2 = v[2];
    }

    int keep = 0;
    const unsigned* maskbase = g_mask + (size_t)img*PRE_NMS*NMS_WORDS;
    const bool has2 = (64 + lane) < NMS_WORDS;

    unsigned c0[SCAN_D], c1[SCAN_D], c2[SCAN_D];
#pragma unroll
    for (int j = 0; j < SCAN_D; j++) {
        const unsigned* mr = maskbase + (size_t)j * NMS_WORDS;
        c0[j] = mr[lane];
        c1[j] = mr[32 + lane];
        c2[j] = has2 ? mr[64 + lane] : 0u;
    }

    for (int i0 = 0; i0 < PRE_NMS; i0 += SCAN_D) {
#pragma unroll
        for (int ph = 0; ph < SCAN_D; ph++) {
            const int i = i0 + ph;
            int w = i >> 5, b = i & 31;
            int slot = w >> 5, owner = w & 31;
            unsigned myw = (slot == 0) ? sup0 : (slot == 1 ? sup1 : sup2);
            unsigned word = __shfl_sync(0xFFFFFFFFu, myw, owner);
            if (!((word >> b) & 1u)) {
                if (keep < POST_NMS && lane == 0) {
                    float4 bx = g_boxes_top[(size_t)img*PRE_NMS + i];
                    float* o = out + OFF_ROIS + ((size_t)img*POST_NMS + keep)*4;
                    o[0] = bx.x; o[1] = bx.y; o[2] = bx.z; o[3] = bx.w;
                }
                keep++;
                sup0 |= c0[ph];
                sup1 |= c1[ph];
                sup2 |= c2[ph];
            }
            const int nx = i + SCAN_D;
            if (nx < PRE_NMS) {
                const unsigned* nr = maskbase + (size_t)nx * NMS_WORDS;
                c0[ph] = nr[lane];
                c1[ph] = nr[32 + lane];
                c2[ph] = has2 ? nr[64 + lane] : 0u;
            } else {
                c0[ph] = 0u; c1[ph] = 0u; c2[ph] = 0u;
            }
        }
    }
}

// =================================================================
// launch
// =================================================================
extern "C" void kernel_launch(void* const* d_in, const int* in_sizes, int n_in,
                              void* d_out, int out_size)
{
    const float* x   = (const float*)d_in[0];
    const void*  ih  = d_in[1];
    const void*  iw  = d_in[2];
    const float* W1  = (const float*)d_in[3];
    const float* b1  = (const float*)d_in[4];
    const float* Ws  = (const float*)d_in[5];
    const float* bs  = (const float*)d_in[6];
    const float* Wl  = (const float*)d_in[7];
    const float* bl  = (const float*)d_in[8];
    float* out = (float*)d_out;

    static int smem_set = 0;
    if (!smem_set) {
        cudaFuncSetAttribute(conv_hmma_kernel,
                             cudaFuncAttributeMaxDynamicSharedMemorySize,
                             SM_CONV_TOTAL);
        smem_set = 1;
    }

    // weight split/pre-swizzle (x64 scale)
    wprep_kernel<<<(4*NCHUNK*128*32 + 255)/256, 256>>>(W1);
    // x split + transpose to fp16 hi/lo
    xsplit_kernel<<<dim3(NPOS/32, CIN/32, N_IMG), dim3(32, 8)>>>(x);
    // anchors -> d_out anchor region (keeps conv as the profiled launch)
    anchor_kernel<<<(A_TOT + 255)/256, 256>>>(out);
    // HMMA split-fp16 3x3 conv + relu (64x64 tiles, 3-stage, 2 CTAs/SM)
    conv_hmma_kernel<<<dim3(8, 64, N_IMG), 256, SM_CONV_TOTAL>>>(b1);
    // 1x1 heads -> d_out locs/scores
    conv1x1_kernel<<<dim3(NPOS/64, N_IMG), 192>>>(Wl, bl, Ws, bs, out);
    // zero rois + roi indices
    fill_kernel<<<(SZ_ROIS + SZ_RIDX + 255)/256, 256>>>(out);
    // proposals + sort keys
    proposal_kernel<<<(N_IMG*A_TOT + 255)/256, 256>>>(out, ih, iw);

    // exact top-3000 selection
    select_kernel<<<N_IMG, 1024>>>();
    compact_kernel<<<dim3(A_TOT/256, N_IMG), 256>>>();
    sortblk_kernel<<<N_IMG, 1024>>>();

    // top-3000 gather
    gather_kernel<<<(N_IMG*PRE_NMS + 255)/256, 256>>>();
    // IoU bitmask (sub-diagonal blocks zero-filled inline)
    mask_kernel<<<dim3(47, 47, N_IMG), 64>>>();
    // sequential NMS scan -> rois
    scan_kernel<<<N_IMG, 32>>>(out);
}

// round 17
// speedup vs baseline: 1.4733x; 1.4733x over previous
#include <cuda_runtime.h>
#include <cuda_fp16.h>
#include <math.h>
#include <stdint.h>

// ---------------- problem constants ----------------
#define N_IMG 4
#define CIN   512
#define HH    64
#define WW    64
#define NPOS  (HH*WW)            // 4096
#define NANCH 9
#define A_TOT (NPOS*NANCH)       // 36864
#define PRE_NMS  3000
#define POST_NMS 300
#define NMS_WORDS 94             // ceil(3000/32)
#define NMS_THRESH 0.7f
#define MIN_SIZE 16.0f

// ---------------- d_out layout (floats), reference return order ----------------
#define SZ_LOCS   (N_IMG*A_TOT*4)            // 589824
#define OFF_LOCS  0
#define SZ_SCORES (N_IMG*A_TOT*2)            // 294912
#define OFF_SCORES (OFF_LOCS+SZ_LOCS)        // 589824
#define SZ_ROIS   (N_IMG*POST_NMS*4)         // 4800
#define OFF_ROIS  (OFF_SCORES+SZ_SCORES)     // 884736
#define SZ_RIDX   (N_IMG*POST_NMS)           // 1200
#define OFF_RIDX  (OFF_ROIS+SZ_ROIS)         // 889536
#define OFF_ANCHOR (OFF_RIDX+SZ_RIDX)        // 890736  (size 147456)

// ---------------- device scratch ----------------
__device__ float               g_hidden[N_IMG*CIN*NPOS];        // 33.5 MB
__device__ float4              g_rois_all[N_IMG*A_TOT];         // 2.36 MB
__device__ unsigned long long  g_keys[N_IMG*A_TOT];             // 1.2 MB
__device__ unsigned long long  g_sel[N_IMG*3072];
__device__ unsigned long long  g_thresh[N_IMG];
__device__ unsigned            g_cnt[N_IMG];
__device__ float4              g_boxes_top[N_IMG*PRE_NMS];      // 192 KB
__device__ float               g_scores_top[N_IMG*PRE_NMS];     // 48 KB
__device__ unsigned            g_mask[(size_t)N_IMG*PRE_NMS*NMS_WORDS]; // 4.5 MB

// split-fp16 weights (scaled x64), pre-swizzled smem-tile layout
#define NCHUNK 72
__device__ uint4 g_wt_hi[4*NCHUNK*1024];   // 4.7 MB
__device__ uint4 g_wt_lo[4*NCHUNK*1024];   // 4.7 MB

// split-fp16 transposed features: [img][pos][cin] fp16
__device__ __half g_xt_hi[(size_t)N_IMG*NPOS*CIN];   // 16.8 MB
__device__ __half g_xt_lo[(size_t)N_IMG*NPOS*CIN];   // 16.8 MB

#define NOUT 54

#define W_SCALE 64.0f
#define W_INV   (1.0f/64.0f)

#define SWZ128(o) ((o) ^ (((o) >> 3) & 0x70))

__device__ __forceinline__ unsigned smem_u32(const void* p) {
    unsigned a;
    asm("{ .reg .u64 t; cvta.to.shared.u64 t, %1; cvt.u32.u64 %0, t; }"
        : "=r"(a) : "l"(p));
    return a;
}

__device__ __forceinline__ void cp_async16(unsigned dst, const void* src, unsigned src_sz)
{
    asm volatile("cp.async.cg.shared.global [%0], [%1], 16, %2;"
                 :: "r"(dst), "l"(src), "r"(src_sz) : "memory");
}
#define CP_COMMIT() asm volatile("cp.async.commit_group;" ::: "memory")
#define CP_WAIT(n)  asm volatile("cp.async.wait_group %0;" :: "n"(n) : "memory")

__device__ __forceinline__ void ldsm4(unsigned& r0, unsigned& r1,
                                      unsigned& r2, unsigned& r3, unsigned addr)
{
    asm volatile("ldmatrix.sync.aligned.m8n8.x4.shared.b16 {%0,%1,%2,%3}, [%4];"
                 : "=r"(r0), "=r"(r1), "=r"(r2), "=r"(r3) : "r"(addr));
}

// fp32-accumulator mma (main term)
__device__ __forceinline__ void mma16816(float* c, const unsigned* a, const unsigned* b)
{
    asm volatile(
        "mma.sync.aligned.m16n8k16.row.col.f32.f16.f16.f32 "
        "{%0,%1,%2,%3}, {%4,%5,%6,%7}, {%8,%9}, {%0,%1,%2,%3};"
        : "+f"(c[0]), "+f"(c[1]), "+f"(c[2]), "+f"(c[3])
        : "r"(a[0]), "r"(a[1]), "r"(a[2]), "r"(a[3]), "r"(b[0]), "r"(b[1]));
}

// fp16-accumulator mma (cross terms)
__device__ __forceinline__ void mma16816h(unsigned* c, const unsigned* a, const unsigned* b)
{
    asm volatile(
        "mma.sync.aligned.m16n8k16.row.col.f16.f16.f16.f16 "
        "{%0,%1}, {%2,%3,%4,%5}, {%6,%7}, {%0,%1};"
        : "+r"(c[0]), "+r"(c[1])
        : "r"(a[0]), "r"(a[1]), "r"(a[2]), "r"(a[3]), "r"(b[0]), "r"(b[1]));
}

// =================================================================
// weight prep (x64 scale, split fp16, pre-swizzled)
// =================================================================
__global__ void wprep_kernel(const float* __restrict__ W1)
{
    int t = blockIdx.x * blockDim.x + threadIdx.x;
    if (t >= 4*NCHUNK*128*32) return;
    int c2 = t & 31;
    int r  = (t >> 5) & 127;
    int tc = t >> 12;
    int ch = tc % NCHUNK;
    int ot = tc / NCHUNK;
    int kk  = ch >> 3;
    int ccb = ch & 7;
    int c  = c2 * 2;
    int cc = ccb*64 + c;
    int oc = ot*128 + r;

    float w0 = W1[(size_t)oc*4608 + (size_t)cc*9 + kk] * W_SCALE;
    float w1 = W1[(size_t)oc*4608 + (size_t)(cc+1)*9 + kk] * W_SCALE;
    __half h0 = __float2half_rn(w0), h1 = __float2half_rn(w1);
    __half l0 = __float2half_rn(w0 - __half2float(h0));
    __half l1 = __float2half_rn(w1 - __half2float(h1));

    unsigned off = (unsigned)(r*128 + c*2);
    off = SWZ128(off);
    size_t base = (size_t)tc * 16384;
    *reinterpret_cast<__half2*>(reinterpret_cast<char*>(g_wt_hi) + base + off) =
        __halves2half2(h0, h1);
    *reinterpret_cast<__half2*>(reinterpret_cast<char*>(g_wt_lo) + base + off) =
        __halves2half2(l0, l1);
}

// =================================================================
// x split + transpose
// =================================================================
__global__ void xsplit_kernel(const float* __restrict__ x)
{
    __shared__ float tile[32][33];
    const int p0  = blockIdx.x * 32;
    const int c0  = blockIdx.y * 32;
    const int img = blockIdx.z;
    const int tx = threadIdx.x, ty = threadIdx.y;

#pragma unroll
    for (int i = 0; i < 4; i++) {
        int c = c0 + ty + i*8;
        tile[ty + i*8][tx] = x[((size_t)img*CIN + c)*NPOS + p0 + tx];
    }
    __syncthreads();

#pragma unroll
    for (int i = 0; i < 4; i++) {
        int p = p0 + ty + i*8;
        float v = tile[tx][ty + i*8];
        __half h = __float2half_rn(v);
        __half l = __float2half_rn(v - __half2float(h));
        size_t o = ((size_t)img*NPOS + p)*CIN + c0 + tx;
        g_xt_hi[o] = h;
        g_xt_lo[o] = l;
    }
}

// =================================================================
// HMMA split-fp16 conv: 128 oc x 64 pos tiles, 2-stage ring, 96 KB
// smem -> 2 CTAs/SM (R15 config: measured 754 us, tensor 57.2%).
// =================================================================
#define BUF_STRIDE 49152
#define SM_AHI 0
#define SM_ALO 16384
#define SM_BHI 32768
#define SM_BLO 40960
#define SM_CONV_TOTAL (2*BUF_STRIDE)     // 98304

__global__ void __launch_bounds__(256, 2) conv_hmma_kernel(const float* __restrict__ b1)
{
    extern __shared__ char smem[];
    const unsigned sbase = smem_u32(smem);
    const int tid  = threadIdx.x;
    const int wid  = tid >> 5;
    const int lane = tid & 31;
    const int ot   = blockIdx.x;          // oc tile 0..3
    const int pt   = blockIdx.y;          // pos tile 0..63 (1 image row)
    const int img  = blockIdx.z;

    const int wm = wid >> 1;              // 0..3 : oc block of 32
    const int wn = wid & 1;               // 0..1 : pos block of 32

    const int sel = lane >> 3;
    const int l7  = lane & 7;

    const int pos0 = pt * 64;
    const int bp  = tid & 63;
    const int kh  = (tid >> 6) & 1;
    const int arr = tid >> 7;             // 0: hi, 1: lo

    float acc[2][4][4];
    unsigned accH[2][4][2];
#pragma unroll
    for (int mt = 0; mt < 2; mt++)
#pragma unroll
        for (int nt = 0; nt < 4; nt++) {
#pragma unroll
            for (int k = 0; k < 4; k++) acc[mt][nt][k] = 0.f;
            accH[mt][nt][0] = 0u;
            accH[mt][nt][1] = 0u;
        }

    const unsigned a_row  = (unsigned)(wm*32 + (sel & 1)*8 + l7);
    const unsigned a_colb = (unsigned)((sel >> 1) * 16);
    const unsigned b_row  = (unsigned)(wn*32 + (sel >> 1)*8 + l7);
    const unsigned b_colb = (unsigned)((sel & 1) * 16);

    const __half* xh_img = g_xt_hi + (size_t)img*NPOS*CIN;
    const __half* xl_img = g_xt_lo + (size_t)img*NPOS*CIN;

    auto issue_chunk = [&](int ch) {
        const unsigned bb = sbase + (unsigned)(ch & 1)*BUF_STRIDE;
        {
            const uint4* sh = g_wt_hi + (size_t)(ot*NCHUNK + ch) * 1024;
            const uint4* sl = g_wt_lo + (size_t)(ot*NCHUNK + ch) * 1024;
#pragma unroll
            for (int i = 0; i < 4; i++) {
                cp_async16(bb + SM_AHI + (tid + i*256)*16, sh + tid + i*256, 16u);
                cp_async16(bb + SM_ALO + (tid + i*256)*16, sl + tid + i*256, 16u);
            }
        }
        {
            const int kk  = ch >> 3;
            const int ccb = ch & 7;
            const int dy  = kk / 3 - 1;
            const int dx  = kk % 3 - 1;
            const int gy  = pt + dy;
            const int gx  = bp + dx;
            const bool valid = (gy >= 0) && (gy < HH) && (gx >= 0) && (gx < WW);
            const unsigned sz = valid ? 16u : 0u;
            const size_t srcoff = ((size_t)(gy*WW + gx))*CIN + ccb*64 + kh*32;
            const __half* src = (arr == 0 ? xh_img : xl_img) + srcoff;
            const unsigned dbase = (arr == 0 ? SM_BHI : SM_BLO);
#pragma unroll
            for (int k = 0; k < 4; k++) {
                unsigned d = SWZ128((unsigned)(bp*128 + kh*64 + k*16));
                cp_async16(bb + dbase + d, src + k*8, sz);
            }
        }
        CP_COMMIT();
    };

    issue_chunk(0);
    issue_chunk(1);

    for (int ch = 0; ch < NCHUNK; ch++) {
        CP_WAIT(1);
        __syncthreads();

        const unsigned bb = sbase + (unsigned)(ch & 1)*BUF_STRIDE;
#pragma unroll
        for (int ks = 0; ks < 4; ks++) {
            const unsigned kcol = (unsigned)(ks * 32);
            unsigned bh[8], bl[8];
            {
                unsigned off0 = SWZ128(b_row*128 + kcol + b_colb);
                unsigned off1 = SWZ128((b_row+16)*128 + kcol + b_colb);
                ldsm4(bh[0], bh[1], bh[2], bh[3], bb + SM_BHI + off0);
                ldsm4(bh[4], bh[5], bh[6], bh[7], bb + SM_BHI + off1);
                ldsm4(bl[0], bl[1], bl[2], bl[3], bb + SM_BLO + off0);
                ldsm4(bl[4], bl[5], bl[6], bl[7], bb + SM_BLO + off1);
            }
#pragma unroll
            for (int mt = 0; mt < 2; mt++) {
                unsigned aoff = SWZ128((a_row + mt*16)*128 + kcol + a_colb);
                unsigned ah[4], al[4];
                ldsm4(ah[0], ah[1], ah[2], ah[3], bb + SM_AHI + aoff);
                ldsm4(al[0], al[1], al[2], al[3], bb + SM_ALO + aoff);
#pragma unroll
                for (int nt = 0; nt < 4; nt++) {
                    mma16816(acc[mt][nt], ah, &bh[nt*2]);     // wh*xh  (fp32 acc)
                    mma16816h(accH[mt][nt], ah, &bl[nt*2]);   // wh*xl  (fp16 acc)
                    mma16816h(accH[mt][nt], al, &bh[nt*2]);   // wl*xh  (fp16 acc)
                }
            }
        }
        __syncthreads();           // done reading stage ch&1
        if (ch + 2 < NCHUNK) issue_chunk(ch + 2);
        else CP_COMMIT();
    }

    const int mrow = lane >> 2;
    const int ncol = (lane & 3) * 2;
#pragma unroll
    for (int mt = 0; mt < 2; mt++) {
        const int ocA = ot*128 + wm*32 + mt*16 + mrow;
        const int ocB = ocA + 8;
        const float biasA = b1[ocA];
        const float biasB = b1[ocB];
#pragma unroll
        for (int nt = 0; nt < 4; nt++) {
            const int pos = pos0 + wn*32 + nt*8 + ncol;
            __half2 cr01 = *reinterpret_cast<__half2*>(&accH[mt][nt][0]);
            __half2 cr23 = *reinterpret_cast<__half2*>(&accH[mt][nt][1]);
            float v0 = (acc[mt][nt][0] + __low2float(cr01))  * W_INV + biasA;
            float v1 = (acc[mt][nt][1] + __high2float(cr01)) * W_INV + biasA;
            float v2 = (acc[mt][nt][2] + __low2float(cr23))  * W_INV + biasB;
            float v3 = (acc[mt][nt][3] + __high2float(cr23)) * W_INV + biasB;
            v0 = v0 > 0.f ? v0 : 0.f;
            v1 = v1 > 0.f ? v1 : 0.f;
            v2 = v2 > 0.f ? v2 : 0.f;
            v3 = v3 > 0.f ? v3 : 0.f;
            *reinterpret_cast<float2*>(
                g_hidden + ((size_t)img*CIN + ocA)*NPOS + pos) = make_float2(v0, v1);
            *reinterpret_cast<float2*>(
                g_hidden + ((size_t)img*CIN + ocB)*NPOS + pos) = make_float2(v2, v3);
        }
    }
}

// =================================================================
// 1x1 convs: output-split (3 groups of 18), sequential channel order
// =================================================================
__global__ __launch_bounds__(192) void conv1x1_kernel(
    const float* __restrict__ Wl, const float* __restrict__ bl,
    const float* __restrict__ Ws, const float* __restrict__ bs,
    float* __restrict__ out)
{
    __shared__ float Wc[64][NOUT];
    const int tid = threadIdx.x;
    const int lp  = tid & 63;
    const int og  = tid >> 6;             // 0..2
    const int o0  = og * 18;
    const int img = blockIdx.y;
    const int pos = blockIdx.x * 64 + lp;

    float acc[18];
#pragma unroll
    for (int o = 0; o < 18; o++) acc[o] = 0.f;

    const float* hid = g_hidden + (size_t)img * CIN * NPOS;

    for (int c0 = 0; c0 < CIN; c0 += 64) {
        for (int idx = tid; idx < 64*NOUT; idx += 192) {
            int c = idx / NOUT;
            int o = idx - c*NOUT;
            Wc[c][o] = (o < 36) ? Wl[(size_t)o*CIN + c0 + c]
                                : Ws[(size_t)(o-36)*CIN + c0 + c];
        }
        __syncthreads();
#pragma unroll 8
        for (int c = 0; c < 64; c++) {
            float h = hid[(size_t)(c0+c)*NPOS + pos];
#pragma unroll
            for (int o = 0; o < 18; o++) acc[o] += h * Wc[c][o0 + o];
        }
        __syncthreads();
    }

#pragma unroll
    for (int o = 0; o < 18; o++) {
        int oo = o0 + o;
        if (oo < 36)
            out[OFF_LOCS + (size_t)img*A_TOT*4 + (size_t)pos*36 + oo] = acc[o] + bl[oo];
        else
            out[OFF_SCORES + (size_t)img*A_TOT*2 + (size_t)pos*18 + (oo-36)] = acc[o] + bs[oo-36];
    }
}

// =================================================================
// anchor generation
// =================================================================
__global__ void anchor_kernel(float* __restrict__ out)
{
    int i = blockIdx.x * blockDim.x + threadIdx.x;
    if (i >= A_TOT) return;
    int a   = i % 9;
    int pos = i / 9;
    int y = pos / WW, x = pos % WW;
    int ri = a / 3, si = a % 3;
    double rr = (ri == 0) ? 0.5 : (ri == 1 ? 1.0 : 2.0);
    double ss = (si == 0) ? 8.0 : (si == 1 ? 16.0 : 32.0);
    double h = 16.0 * ss * sqrt(rr);
    double w = 16.0 * ss * sqrt(1.0 / rr);
    float ymin = (float)(8.0 - h*0.5);
    float xmin = (float)(8.0 - w*0.5);
    float ymax = (float)(8.0 + h*0.5);
    float xmax = (float)(8.0 + w*0.5);
    float sy = (float)y * 16.0f, sx = (float)x * 16.0f;
    reinterpret_cast<float4*>(out + OFF_ANCHOR)[i] =
        make_float4(sy + ymin, sx + xmin, sy + ymax, sx + xmax);
}

// =================================================================
// proposal: loc2bbox + clip + min-size + softmax + sort key
// =================================================================
__device__ __forceinline__ float read_dim(const void* p)
{
    int v = *(const int*)p;
    if (v > 0 && v < (1 << 20)) return (float)v;
    return *(const float*)p;
}

__global__ void proposal_kernel(const float* __restrict__ out,
                                const void* __restrict__ p_ih,
                                const void* __restrict__ p_iw)
{
    int t = blockIdx.x * blockDim.x + threadIdx.x;
    if (t >= N_IMG * A_TOT) return;
    int img = t / A_TOT;
    int i   = t - img * A_TOT;

    const float4 anc = reinterpret_cast<const float4*>(out + OFF_ANCHOR)[i];
    const float* loc = out + OFF_LOCS + (size_t)img*A_TOT*4 + (size_t)i*4;
    const float l0 = loc[0], l1 = loc[1], l2 = loc[2], l3 = loc[3];
    const float* sc = out + OFF_SCORES + (size_t)img*A_TOT*2 + (size_t)i*2;
    const float s0 = sc[0], s1 = sc[1];

    float h  = anc.z - anc.x, w = anc.w - anc.y;
    float cy = anc.x + 0.5f*h, cx = anc.y + 0.5f*w;
    float ncy = l0*h + cy, ncx = l1*w + cx;
    float nh  = expf(l2)*h,  nw  = expf(l3)*w;

    float fh = read_dim(p_ih), fw = read_dim(p_iw);
    float y1 = fminf(fmaxf(ncy - 0.5f*nh, 0.f), fh);
    float x1 = fminf(fmaxf(ncx - 0.5f*nw, 0.f), fw);
    float y2 = fminf(fmaxf(ncy + 0.5f*nh, 0.f), fh);
    float x2 = fminf(fmaxf(ncx + 0.5f*nw, 0.f), fw);

    bool ok = ((y2 - y1) >= MIN_SIZE) && ((x2 - x1) >= MIN_SIZE);

    float m  = fmaxf(s0, s1);
    float e0 = expf(s0 - m), e1 = expf(s1 - m);
    float fg = e1 / (e0 + e1);
    float score = ok ? fg : -INFINITY;

    g_rois_all[(size_t)img*A_TOT + i] = make_float4(y1, x1, y2, x2);

    unsigned u    = __float_as_uint(score);
    unsigned mkey = u ^ ((u >> 31) ? 0xFFFFFFFFu : 0x80000000u);
    unsigned dkey = ~mkey;
    g_keys[(size_t)img*A_TOT + i] = ((unsigned long long)dkey << 32) | (unsigned)i;
}

// =================================================================
// radix-select: exact 3000th-smallest key per image (per-warp hists)
// =================================================================
__global__ __launch_bounds__(1024) void select_kernel()
{
    __shared__ unsigned hist[32][256];
    __shared__ unsigned cnt[256];
    __shared__ unsigned long long s_prefix;
    __shared__ int s_remaining;

    const int img  = blockIdx.x;
    const int tid  = threadIdx.x;
    const int wrp  = tid >> 5;
    const unsigned long long* keys = g_keys + (size_t)img*A_TOT;

    unsigned long long kreg[36];
#pragma unroll
    for (int j = 0; j < 36; j++) kreg[j] = keys[tid + j*1024];

    if (tid == 0) { s_prefix = 0; s_remaining = PRE_NMS; g_cnt[img] = 0; }
    __syncthreads();

    for (int s = 0; s < 8; s++) {
        for (int b = tid; b < 32*256; b += 1024)
            reinterpret_cast<unsigned*>(hist)[b] = 0;
        __syncthreads();
        const unsigned long long pfx = s_prefix;
        const int shift = 56 - 8*s;
#pragma unroll
        for (int j = 0; j < 36; j++) {
            unsigned long long k = kreg[j];
            bool match = (s == 0) || ((k >> (64 - 8*s)) == pfx);
            if (match) atomicAdd(&hist[wrp][(unsigned)((k >> shift) & 0xFF)], 1u);
        }
        __syncthreads();
        if (tid < 256) {
            unsigned c = 0;
#pragma unroll
            for (int w = 0; w < 32; w++) c += hist[w][tid];
            cnt[tid] = c;
        }
        __syncthreads();
        if (tid == 0) {
            unsigned c = 0;
            int b = 0;
            int rem = s_remaining;
            for (; b < 256; b++) {
                c += cnt[b];
                if ((int)c >= rem) break;
            }
            s_remaining = rem - (int)(c - cnt[b]);
            s_prefix = (s_prefix << 8) | (unsigned long long)b;
        }
        __syncthreads();
    }
    if (tid == 0) g_thresh[img] = s_prefix;
}

// =================================================================
// compact keys <= threshold (exactly 3000, unordered)
// =================================================================
__global__ void compact_kernel()
{
    const int img = blockIdx.y;
    const int i   = blockIdx.x * 256 + threadIdx.x;
    const int lane = threadIdx.x & 31;

    unsigned long long T = g_thresh[img];
    unsigned long long k = g_keys[(size_t)img*A_TOT + i];
    bool sel = (k <= T);

    unsigned mask = __ballot_sync(0xFFFFFFFFu, sel);
    if (sel) {
        int leader = __ffs(mask) - 1;
        unsigned base = 0;
        if (lane == leader) base = atomicAdd(&g_cnt[img], (unsigned)__popc(mask));
        base = __shfl_sync(0xFFFFFFFFu, base, leader);
        int off = __popc(mask & ((1u << lane) - 1u));
        g_sel[(size_t)img*3072 + base + off] = k;
    }
}

// =================================================================
// single-block bitonic sort of 3000 keys (pad to 4096), ascending
// =================================================================
__global__ __launch_bounds__(1024) void sortblk_kernel()
{
    __shared__ unsigned long long sk[4096];
    const int img = blockIdx.x;
    const int tid = threadIdx.x;

#pragma unroll
    for (int j = 0; j < 4; j++) {
        int i = tid + j*1024;
        sk[i] = (i < PRE_NMS) ? g_sel[(size_t)img*3072 + i] : ~0ULL;
    }
    __syncthreads();

    for (int k = 2; k <= 4096; k <<= 1) {
        for (int j = k >> 1; j > 0; j >>= 1) {
#pragma unroll
            for (int t = 0; t < 2; t++) {
                int tt  = tid + t*1024;
                int i   = ((tt & ~(j - 1)) << 1) | (tt & (j - 1));
                int ixj = i | j;
                bool up = ((i & k) == 0);
                unsigned long long a = sk[i], b = sk[ixj];
                if ((a > b) == up) { sk[i] = b; sk[ixj] = a; }
            }
            __syncthreads();
        }
    }

#pragma unroll
    for (int j = 0; j < 3; j++) {
        int i = tid + j*1024;
        if (i < PRE_NMS) g_keys[(size_t)img*A_TOT + i] = sk[i];
    }
}

// =================================================================
// gather top-3000 boxes + scores
// =================================================================
__global__ void gather_kernel()
{
    int t = blockIdx.x * blockDim.x + threadIdx.x;
    if (t >= N_IMG * PRE_NMS) return;
    int img = t / PRE_NMS;
    int i   = t - img * PRE_NMS;
    unsigned long long key = g_keys[(size_t)img*A_TOT + i];
    unsigned idx = (unsigned)(key & 0xFFFFFFFFu);
    g_boxes_top[t] = g_rois_all[(size_t)img*A_TOT + idx];
    unsigned dkey = (unsigned)(key >> 32);
    unsigned mkey = ~dkey;
    unsigned u = (mkey & 0x80000000u) ? (mkey ^ 0x80000000u) : ~mkey;
    g_scores_top[t] = __uint_as_float(u);
}

// =================================================================
// NMS suppression bitmask; sub-diagonal blocks just write zeros
// =================================================================
__global__ __launch_bounds__(64) void mask_kernel()
{
    const int img  = blockIdx.z;
    const int rowb = blockIdx.y * 64;
    const int colb = blockIdx.x * 64;
    const int t = threadIdx.x;

    if (colb + 63 <= rowb) {
        int row = rowb + t;
        if (row < PRE_NMS) {
            unsigned* mrow = g_mask + ((size_t)img*PRE_NMS + row) * NMS_WORDS;
            int wi = colb >> 5;
            mrow[wi] = 0u;
            if (wi + 1 < NMS_WORDS) mrow[wi + 1] = 0u;
        }
        return;
    }

    __shared__ float4 cb[64];
    int col0 = colb + t;
    cb[t] = (col0 < PRE_NMS) ? g_boxes_top[(size_t)img*PRE_NMS + col0]
                             : make_float4(0.f, 0.f, 0.f, 0.f);
    __syncthreads();

    int row = rowb + t;
    if (row >= PRE_NMS) return;
    float4 rb = g_boxes_top[(size_t)img*PRE_NMS + row];
    float ra = fmaxf(rb.z - rb.x, 0.f) * fmaxf(rb.w - rb.y, 0.f);

    unsigned w0 = 0, w1 = 0;
#pragma unroll 4
    for (int c = 0; c < 64; c++) {
        int col = colb + c;
        if (col >= PRE_NMS || col <= row) continue;
        float4 b = cb[c];
        float yy1 = fmaxf(rb.x, b.x), xx1 = fmaxf(rb.y, b.y);
        float yy2 = fminf(rb.z, b.z), xx2 = fminf(rb.w, b.w);
        float inter = fmaxf(yy2 - yy1, 0.f) * fmaxf(xx2 - xx1, 0.f);
        float ba = fmaxf(b.z - b.x, 0.f) * fmaxf(b.w - b.y, 0.f);
        float iou = inter / (ra + ba - inter + 1e-9f);
        if (iou > NMS_THRESH) {
            if (c < 32) w0 |= 1u << c; else w1 |= 1u << (c - 32);
        }
    }
    unsigned* mrow = g_mask + ((size_t)img*PRE_NMS + row) * NMS_WORDS;
    int wi = colb >> 5;
    mrow[wi] = w0;
    if (wi + 1 < NMS_WORDS) mrow[wi + 1] = w1;
}

// =================================================================
// zero rois region + write roi_indices
// =================================================================
__global__ void fill_kernel(float* __restrict__ out)
{
    int t = blockIdx.x * blockDim.x + threadIdx.x;
    if (t < SZ_ROIS) out[OFF_ROIS + t] = 0.f;
    else if (t < SZ_ROIS + SZ_RIDX) {
        int i = t - SZ_ROIS;
        out[OFF_RIDX + i] = (float)(i / POST_NMS);
    }
}

// =================================================================
// sequential greedy NMS scan, 8-deep pipelined mask loads,
// EARLY EXIT once POST_NMS boxes kept (output-invariant: rows
// examined after the 300th keep can never be written).
// =================================================================
#define SCAN_D 8
__global__ void scan_kernel(float* __restrict__ out)
{
    const int img  = blockIdx.x;
    const int lane = threadIdx.x;

    unsigned sup0, sup1, sup2;
    {
        unsigned v[3];
#pragma unroll
        for (int s = 0; s < 3; s++) {
            unsigned vv = 0;
            int w = s*32 + lane;
            for (int b = 0; b < 32; b++) {
                int i = w*32 + b;
                if (i < PRE_NMS && g_scores_top[(size_t)img*PRE_NMS + i] == -INFINITY)
                    vv |= 1u << b;
            }
            v[s] = vv;
        }
        sup0 = v[0]; sup1 = v[1]; sup2 = v[2];
    }

    int keep = 0;
    const unsigned* maskbase = g_mask + (size_t)img*PRE_NMS*NMS_WORDS;
    const bool has2 = (64 + lane) < NMS_WORDS;

    unsigned c0[SCAN_D], c1[SCAN_D], c2[SCAN_D];
#pragma unroll
    for (int j = 0; j < SCAN_D; j++) {
        const unsigned* mr = maskbase + (size_t)j * NMS_WORDS;
        c0[j] = mr[lane];
        c1[j] = mr[32 + lane];
        c2[j] = has2 ? mr[64 + lane] : 0u;
    }

    for (int i0 = 0; i0 < PRE_NMS; i0 += SCAN_D) {
#pragma unroll
        for (int ph = 0; ph < SCAN_D; ph++) {
            const int i = i0 + ph;
            int w = i >> 5, b = i & 31;
            int slot = w >> 5, owner = w & 31;
            unsigned myw = (slot == 0) ? sup0 : (slot == 1 ? sup1 : sup2);
            unsigned word = __shfl_sync(0xFFFFFFFFu, myw, owner);
            if (!((word >> b) & 1u)) {
                if (lane == 0) {
                    float4 bx = g_boxes_top[(size_t)img*PRE_NMS + i];
                    float* o = out + OFF_ROIS + ((size_t)img*POST_NMS + keep)*4;
                    o[0] = bx.x; o[1] = bx.y; o[2] = bx.z; o[3] = bx.w;
                }
                keep++;
                if (keep >= POST_NMS) return;   // uniform across warp
                sup0 |= c0[ph];
                sup1 |= c1[ph];
                sup2 |= c2[ph];
            }
            const int nx = i + SCAN_D;
            if (nx < PRE_NMS) {
                const unsigned* nr = maskbase + (size_t)nx * NMS_WORDS;
                c0[ph] = nr[lane];
                c1[ph] = nr[32 + lane];
                c2[ph] = has2 ? nr[64 + lane] : 0u;
            } else {
                c0[ph] = 0u; c1[ph] = 0u; c2[ph] = 0u;
            }
        }
    }
}

// =================================================================
// launch
// =================================================================
extern "C" void kernel_launch(void* const* d_in, const int* in_sizes, int n_in,
                              void* d_out, int out_size)
{
    const float* x   = (const float*)d_in[0];
    const void*  ih  = d_in[1];
    const void*  iw  = d_in[2];
    const float* W1  = (const float*)d_in[3];
    const float* b1  = (const float*)d_in[4];
    const float* Ws  = (const float*)d_in[5];
    const float* bs  = (const float*)d_in[6];
    const float* Wl  = (const float*)d_in[7];
    const float* bl  = (const float*)d_in[8];
    float* out = (float*)d_out;

    static int smem_set = 0;
    if (!smem_set) {
        cudaFuncSetAttribute(conv_hmma_kernel,
                             cudaFuncAttributeMaxDynamicSharedMemorySize,
                             SM_CONV_TOTAL);
        smem_set = 1;
    }

    // weight split/pre-swizzle (x64 scale)
    wprep_kernel<<<(4*NCHUNK*128*32 + 255)/256, 256>>>(W1);
    // x split + transpose to fp16 hi/lo
    xsplit_kernel<<<dim3(NPOS/32, CIN/32, N_IMG), dim3(32, 8)>>>(x);
    // anchors -> d_out anchor region (keeps conv as the profiled launch)
    anchor_kernel<<<(A_TOT + 255)/256, 256>>>(out);
    // HMMA split-fp16 3x3 conv + relu (R15 config: 128oc x 64pos, 2 CTAs/SM)
    conv_hmma_kernel<<<dim3(4, 64, N_IMG), 256, SM_CONV_TOTAL>>>(b1);
    // 1x1 heads -> d_out locs/scores
    conv1x1_kernel<<<dim3(NPOS/64, N_IMG), 192>>>(Wl, bl, Ws, bs, out);
    // zero rois + roi indices
    fill_kernel<<<(SZ_ROIS + SZ_RIDX + 255)/256, 256>>>(out);
    // proposals + sort keys
    proposal_kernel<<<(N_IMG*A_TOT + 255)/256, 256>>>(out, ih, iw);

    // exact top-3000 selection
    select_kernel<<<N_IMG, 1024>>>();
    compact_kernel<<<dim3(A_TOT/256, N_IMG), 256>>>();
    sortblk_kernel<<<N_IMG, 1024>>>();

    // top-3000 gather
    gather_kernel<<<(N_IMG*PRE_NMS + 255)/256, 256>>>();
    // IoU bitmask (sub-diagonal blocks zero-filled inline)
    mask_kernel<<<dim3(47, 47, N_IMG), 64>>>();
    // sequential NMS scan -> rois (early exit at 300 keeps)
    scan_kernel<<<N_IMG, 32>>>(out);
}